// round 1
// baseline (speedup 1.0000x reference)
#include <cuda_runtime.h>
#include <math.h>

#define T_STEPS 8
#define NN      20000
#define FIN_DIM 32
#define EE      160000
#define HID     128
#define G3      384

typedef unsigned long long u64;

// ------------------------- scratch (device globals) -------------------------
__device__ float g_h[(size_t)T_STEPS * NN * HID];   // gru_out then h_stack
__device__ float g_tmp[(size_t)NN * HID];           // conv layer ping buffer / h_attn
__device__ float g_q[(size_t)NN * HID];
__device__ float g_k[(size_t)NN * HID];
__device__ float g_v[(size_t)NN * HID];
__device__ float g_gi[(size_t)NN * G3];
__device__ float g_gh[(size_t)NN * G3];
__device__ float g_hprev[(size_t)NN * HID];
__device__ float g_alpha[EE];
__device__ int   g_amax[NN];
__device__ float g_denom[NN];
__device__ float g_hattn[(size_t)NN * HID];

// ------------------------------- helpers ------------------------------------
__device__ __forceinline__ float warp_sum(float v) {
#pragma unroll
    for (int o = 16; o; o >>= 1) v += __shfl_xor_sync(0xffffffffu, v, o);
    return v;
}
// monotonic float<->int mapping so atomicMax(int) == float max
__device__ __forceinline__ int f2ord(float f) { int i = __float_as_int(f); return i >= 0 ? i : i ^ 0x7fffffff; }
__device__ __forceinline__ float ord2f(int i) { return __int_as_float(i >= 0 ? i : i ^ 0x7fffffff); }

__device__ __forceinline__ u64 pk2(float lo, float hi) {
    u64 r; asm("mov.b64 %0,{%1,%2};" : "=l"(r) : "f"(lo), "f"(hi)); return r;
}
__device__ __forceinline__ void up2(u64 v, float& lo, float& hi) {
    asm("mov.b64 {%0,%1},%2;" : "=f"(lo), "=f"(hi) : "l"(v));
}
// packed dual-FMA (FFMA2) — full-rate fp32 path on sm_103a
__device__ __forceinline__ void ffma2(u64& d, u64 a, u64 b) {
    asm("fma.rn.f32x2 %0,%1,%2,%0;" : "+l"(d) : "l"(a), "l"(b));
}
__device__ __forceinline__ float sigf(float x) { return 1.0f / (1.0f + expf(-x)); }

// --------------------------- SGEMM (C = A @ W^T + b) -------------------------
// A:[nrows,K] row-major, W:[M,K] row-major, C:[nrows,M]. K%16==0, M%64==0.
__global__ void __launch_bounds__(256) sgemm_nt_bias(
    const float* __restrict__ A, const float* __restrict__ W,
    const float* __restrict__ bias, float* __restrict__ C,
    int nrows, int K, int M)
{
    __shared__ float As[16][68];
    __shared__ float Bs[16][68];
    const int tid = threadIdx.x;
    const int tx = tid & 15, ty = tid >> 4;
    const int brow = blockIdx.y << 6, bcol = blockIdx.x << 6;
    const int lrow = tid >> 2;
    const int lk = (tid & 3) << 2;

    u64 acc[4][2];
#pragma unroll
    for (int i = 0; i < 4; i++) { acc[i][0] = 0ull; acc[i][1] = 0ull; }

    const int ar = brow + lrow;
    const float* Arow = A + (size_t)ar * K;
    const float* Wrow = W + (size_t)(bcol + lrow) * K;

    for (int k0 = 0; k0 < K; k0 += 16) {
        float4 av = (ar < nrows) ? *(const float4*)(Arow + k0 + lk) : make_float4(0.f, 0.f, 0.f, 0.f);
        float4 wv = *(const float4*)(Wrow + k0 + lk);
        As[lk + 0][lrow] = av.x; As[lk + 1][lrow] = av.y; As[lk + 2][lrow] = av.z; As[lk + 3][lrow] = av.w;
        Bs[lk + 0][lrow] = wv.x; Bs[lk + 1][lrow] = wv.y; Bs[lk + 2][lrow] = wv.z; Bs[lk + 3][lrow] = wv.w;
        __syncthreads();
#pragma unroll
        for (int kk = 0; kk < 16; kk++) {
            float a0 = As[kk][(ty << 2) + 0], a1 = As[kk][(ty << 2) + 1];
            float a2 = As[kk][(ty << 2) + 2], a3 = As[kk][(ty << 2) + 3];
            float b0 = Bs[kk][(tx << 2) + 0], b1 = Bs[kk][(tx << 2) + 1];
            float b2 = Bs[kk][(tx << 2) + 2], b3 = Bs[kk][(tx << 2) + 3];
            u64 b01 = pk2(b0, b1), b23 = pk2(b2, b3);
            u64 t;
            t = pk2(a0, a0); ffma2(acc[0][0], t, b01); ffma2(acc[0][1], t, b23);
            t = pk2(a1, a1); ffma2(acc[1][0], t, b01); ffma2(acc[1][1], t, b23);
            t = pk2(a2, a2); ffma2(acc[2][0], t, b01); ffma2(acc[2][1], t, b23);
            t = pk2(a3, a3); ffma2(acc[3][0], t, b01); ffma2(acc[3][1], t, b23);
        }
        __syncthreads();
    }

    const int cc = bcol + (tx << 2);
    const float bv0 = bias[cc], bv1 = bias[cc + 1], bv2 = bias[cc + 2], bv3 = bias[cc + 3];
#pragma unroll
    for (int i = 0; i < 4; i++) {
        int r = brow + (ty << 2) + i;
        if (r >= nrows) continue;
        float o0, o1, o2, o3;
        up2(acc[i][0], o0, o1); up2(acc[i][1], o2, o3);
        float* Cp = C + (size_t)r * M + cc;
        Cp[0] = o0 + bv0; Cp[1] = o1 + bv1; Cp[2] = o2 + bv2; Cp[3] = o3 + bv3;
    }
}

// ------------------------------- GRU gates ----------------------------------
__global__ void gru_gate(const float* __restrict__ gi, const float* __restrict__ gh,
                         float* __restrict__ hprev, float* __restrict__ hout)
{
    int idx = blockIdx.x * blockDim.x + threadIdx.x;
    if (idx >= NN * HID) return;
    int n = idx / HID, c = idx % HID;
    const float* gin = gi + (size_t)n * G3;
    const float* ghn = gh + (size_t)n * G3;
    float r = sigf(gin[c] + ghn[c]);
    float z = sigf(gin[HID + c] + ghn[HID + c]);
    float nn = tanhf(gin[2 * HID + c] + r * ghn[2 * HID + c]);
    float hp = hprev[idx];
    float hn = (1.0f - z) * nn + z * hp;
    hprev[idx] = hn;
    hout[idx] = hn;
}

// ------------------------- segment softmax helpers --------------------------
__global__ void init_seg(int* __restrict__ amax, float* __restrict__ denom)
{
    int i = blockIdx.x * blockDim.x + threadIdx.x;
    if (i < NN) { amax[i] = f2ord(-INFINITY); denom[i] = 0.0f; }
}

// alpha[e] = dot(q[dst], k[src] + ea*We)/sqrt(HID); segment max over dst
__global__ void __launch_bounds__(256) edge_alpha(
    const float* __restrict__ q, const float* __restrict__ k,
    const int* __restrict__ src, const int* __restrict__ dst,
    const float* __restrict__ ea, const float* __restrict__ We,
    float* __restrict__ alpha, int* __restrict__ amax)
{
    int e = (blockIdx.x * blockDim.x + threadIdx.x) >> 5;
    int lane = threadIdx.x & 31;
    if (e >= EE) return;
    int s = src[e], d = dst[e];
    float eav = ea[e];
    const float* qd = q + (size_t)d * HID;
    const float* ks = k + (size_t)s * HID;
    float p = 0.0f;
#pragma unroll
    for (int i = lane; i < HID; i += 32)
        p = fmaf(qd[i], ks[i] + eav * We[i], p);
    p = warp_sum(p);
    if (lane == 0) {
        p *= 0.08838834764831845f;  // 1/sqrt(128)
        alpha[e] = p;
        atomicMax(&amax[d], f2ord(p));
    }
}

// ex = exp(alpha - amax[dst]); denom[dst] += ex  (generic, scalar)
__global__ void edge_ex(const int* __restrict__ dst, float* __restrict__ alpha,
                        const int* __restrict__ amax, float* __restrict__ denom)
{
    int e = blockIdx.x * blockDim.x + threadIdx.x;
    if (e >= EE) return;
    int d = dst[e];
    float ex = expf(alpha[e] - ord2f(amax[d]));
    alpha[e] = ex;
    atomicAdd(&denom[d], ex);
}

// out[dst] += a * (v[src] + ea*We) using vec4 global reductions
__global__ void __launch_bounds__(256) edge_msg(
    const float* __restrict__ v,
    const int* __restrict__ src, const int* __restrict__ dst,
    const float* __restrict__ ea, const float* __restrict__ We,
    const float* __restrict__ ex, const float* __restrict__ denom,
    float* __restrict__ out)
{
    int e = (blockIdx.x * blockDim.x + threadIdx.x) >> 5;
    int lane = threadIdx.x & 31;
    if (e >= EE) return;
    int s = src[e], d = dst[e];
    float eav = ea[e];
    float a = ex[e] / (denom[d] + 1e-16f);
    int i = lane << 2;
    float4 vv = *(const float4*)(v + (size_t)s * HID + i);
    float4 wv = *(const float4*)(We + i);
    float m0 = a * (vv.x + eav * wv.x);
    float m1 = a * (vv.y + eav * wv.y);
    float m2 = a * (vv.z + eav * wv.z);
    float m3 = a * (vv.w + eav * wv.w);
    float* p = out + (size_t)d * HID + i;
    asm volatile("red.global.add.v4.f32 [%0], {%1,%2,%3,%4};"
                 :: "l"(p), "f"(m0), "f"(m1), "f"(m2), "f"(m3) : "memory");
}

__global__ void leaky_relu_k(float* __restrict__ x)
{
    int i = blockIdx.x * blockDim.x + threadIdx.x;
    if (i >= NN * HID) return;
    float v = x[i];
    x[i] = v > 0.0f ? v : 0.01f * v;
}

// --------------------- temporal attention + top-k (warp/node) ---------------
__global__ void __launch_bounds__(256) attn_topk(
    const float* __restrict__ h, const float* __restrict__ W,
    const float* __restrict__ b, float* __restrict__ hattn)
{
    int n = (blockIdx.x * blockDim.x + threadIdx.x) >> 5;
    int lane = threadIdx.x & 31;
    if (n >= NN) return;
    float s[T_STEPS];
#pragma unroll
    for (int t = 0; t < T_STEPS; t++) {
        const float* row = h + ((size_t)t * NN + n) * HID;
        float p = 0.0f;
#pragma unroll
        for (int i = lane; i < HID; i += 32) p = fmaf(row[i], W[i], p);
        s[t] = warp_sum(p) + b[0];
    }
    float mx = s[0];
#pragma unroll
    for (int t = 1; t < T_STEPS; t++) mx = fmaxf(mx, s[t]);
    float aw[T_STEPS]; float tot = 0.0f;
#pragma unroll
    for (int t = 0; t < T_STEPS; t++) { aw[t] = expf(s[t] - mx); tot += aw[t]; }
    float inv = 1.0f / tot;
#pragma unroll
    for (int t = 0; t < T_STEPS; t++) aw[t] *= inv;
    // top-3 selection (ties -> lower index, matching lax.top_k)
    bool sel[T_STEPS];
#pragma unroll
    for (int t = 0; t < T_STEPS; t++) sel[t] = false;
    float sum3 = 0.0f;
#pragma unroll
    for (int r = 0; r < 3; r++) {
        float best = -1.0f; int bi = 0;
#pragma unroll
        for (int t = 0; t < T_STEPS; t++)
            if (!sel[t] && aw[t] > best) { best = aw[t]; bi = t; }
        sel[bi] = true; sum3 += best;
    }
    float winv = 1.0f / (sum3 + 1e-8f);
    float w[T_STEPS];
#pragma unroll
    for (int t = 0; t < T_STEPS; t++) w[t] = sel[t] ? aw[t] * winv : 0.0f;
#pragma unroll
    for (int i = lane; i < HID; i += 32) {
        float acc = 0.0f;
#pragma unroll
        for (int t = 0; t < T_STEPS; t++)
            acc = fmaf(w[t], h[((size_t)t * NN + n) * HID + i], acc);
        hattn[(size_t)n * HID + i] = acc;
    }
}

// ------------------------- output conv (C_out = 1) --------------------------
__global__ void __launch_bounds__(256) outconv_node(
    const float* __restrict__ x,
    const float* __restrict__ Wq, const float* __restrict__ bq,
    const float* __restrict__ Wk, const float* __restrict__ bk,
    const float* __restrict__ Wv, const float* __restrict__ bv,
    const float* __restrict__ Ws, const float* __restrict__ bs,
    float* __restrict__ qs, float* __restrict__ ks,
    float* __restrict__ vs, float* __restrict__ outp)
{
    int n = (blockIdx.x * blockDim.x + threadIdx.x) >> 5;
    int lane = threadIdx.x & 31;
    if (n >= NN) return;
    const float* xr = x + (size_t)n * HID;
    float pq = 0.f, pk = 0.f, pv = 0.f, ps = 0.f;
#pragma unroll
    for (int i = lane; i < HID; i += 32) {
        float xv = xr[i];
        pq = fmaf(xv, Wq[i], pq);
        pk = fmaf(xv, Wk[i], pk);
        pv = fmaf(xv, Wv[i], pv);
        ps = fmaf(xv, Ws[i], ps);
    }
    pq = warp_sum(pq); pk = warp_sum(pk); pv = warp_sum(pv); ps = warp_sum(ps);
    if (lane == 0) {
        qs[n] = pq + bq[0];
        ks[n] = pk + bk[0];
        vs[n] = pv + bv[0];
        outp[n] = ps + bs[0];   // skip term initializes the aggregator
    }
}

__global__ void oc_alpha(const float* __restrict__ qs, const float* __restrict__ ks,
                         const int* __restrict__ src, const int* __restrict__ dst,
                         const float* __restrict__ ea, const float* __restrict__ We,
                         float* __restrict__ alpha, int* __restrict__ amax)
{
    int e = blockIdx.x * blockDim.x + threadIdx.x;
    if (e >= EE) return;
    int s = src[e], d = dst[e];
    float a = qs[d] * (ks[s] + ea[e] * We[0]);   // C=1 -> /sqrt(1)
    alpha[e] = a;
    atomicMax(&amax[d], f2ord(a));
}

__global__ void oc_msg(const float* __restrict__ vs,
                       const int* __restrict__ src, const int* __restrict__ dst,
                       const float* __restrict__ ea, const float* __restrict__ We,
                       const float* __restrict__ ex, const float* __restrict__ denom,
                       float* __restrict__ outp)
{
    int e = blockIdx.x * blockDim.x + threadIdx.x;
    if (e >= EE) return;
    int s = src[e], d = dst[e];
    float a = ex[e] / (denom[d] + 1e-16f);
    atomicAdd(&outp[d], a * (vs[s] + ea[e] * We[0]));
}

// --------------------------------- host -------------------------------------
static float* symf(const void* sym) { void* p = nullptr; cudaGetSymbolAddress(&p, sym); return (float*)p; }

extern "C" void kernel_launch(void* const* d_in, const int* in_sizes, int n_in,
                              void* d_out, int out_size)
{
    const float* x_seq = (const float*)d_in[0];
    const int*   ei    = (const int*)d_in[1];
    const float* ea    = (const float*)d_in[2];
    const float* W_ih  = (const float*)d_in[3];
    const float* W_hh  = (const float*)d_in[4];
    const float* b_ih  = (const float*)d_in[5];
    const float* b_hh  = (const float*)d_in[6];
    const float* cWq = (const float*)d_in[7];  const float* cbq = (const float*)d_in[8];
    const float* cWk = (const float*)d_in[9];  const float* cbk = (const float*)d_in[10];
    const float* cWv = (const float*)d_in[11]; const float* cbv = (const float*)d_in[12];
    const float* cWe = (const float*)d_in[13];
    const float* cWs = (const float*)d_in[14]; const float* cbs = (const float*)d_in[15];
    const float* oWq = (const float*)d_in[16]; const float* obq = (const float*)d_in[17];
    const float* oWk = (const float*)d_in[18]; const float* obk = (const float*)d_in[19];
    const float* oWv = (const float*)d_in[20]; const float* obv = (const float*)d_in[21];
    const float* oWe = (const float*)d_in[22];
    const float* oWs = (const float*)d_in[23]; const float* obs = (const float*)d_in[24];
    const float* aW  = (const float*)d_in[25]; const float* ab  = (const float*)d_in[26];
    float* outp = (float*)d_out;

    float* ph     = symf(g_h);
    float* ptmp   = symf(g_tmp);
    float* pq     = symf(g_q);
    float* pk     = symf(g_k);
    float* pv     = symf(g_v);
    float* pgi    = symf(g_gi);
    float* pgh    = symf(g_gh);
    float* phprev = symf(g_hprev);
    float* palpha = symf(g_alpha);
    int*   pamax  = (int*)symf(g_amax);
    float* pdenom = symf(g_denom);
    float* phattn = symf(g_hattn);

    const int nwblk   = (NN + 7) / 8;           // warp-per-node kernels
    const int ewblk   = (EE + 7) / 8;           // warp-per-edge kernels
    const int esblk   = (EE + 255) / 256;       // thread-per-edge kernels
    const int nsblk   = (NN + 255) / 256;
    const int nhblk   = (NN * HID + 255) / 256;
    const dim3 ggh(HID / 64, (NN + 63) / 64);   // GEMM grid, M=128
    const dim3 gg3(G3 / 64, (NN + 63) / 64);    // GEMM grid, M=384

    // ---------------- GRU over T steps ----------------
    cudaMemsetAsync(phprev, 0, (size_t)NN * HID * sizeof(float));
    for (int t = 0; t < T_STEPS; t++) {
        sgemm_nt_bias<<<gg3, 256>>>(x_seq + (size_t)t * NN * FIN_DIM, W_ih, b_ih, pgi, NN, FIN_DIM, G3);
        sgemm_nt_bias<<<gg3, 256>>>(phprev, W_hh, b_hh, pgh, NN, HID, G3);
        gru_gate<<<nhblk, 256>>>(pgi, pgh, phprev, ph + (size_t)t * NN * HID);
    }

    // ---------------- GNN: 2 TransformerConv layers per t ----------------
    for (int t = 0; t < T_STEPS; t++) {
        const int* src = ei + (size_t)t * 2 * EE;
        const int* dst = src + EE;
        const float* eat = ea + (size_t)t * EE;
        float* xt = ph + (size_t)t * NN * HID;

        for (int l = 0; l < 2; l++) {
            const float* in  = (l == 0) ? xt : ptmp;
            float*       out = (l == 0) ? ptmp : xt;
            const float* Wq = cWq + (size_t)l * HID * HID; const float* bq = cbq + (size_t)l * HID;
            const float* Wk = cWk + (size_t)l * HID * HID; const float* bk = cbk + (size_t)l * HID;
            const float* Wv = cWv + (size_t)l * HID * HID; const float* bv = cbv + (size_t)l * HID;
            const float* We = cWe + (size_t)l * HID;
            const float* Ws = cWs + (size_t)l * HID * HID; const float* bs = cbs + (size_t)l * HID;

            sgemm_nt_bias<<<ggh, 256>>>(in, Wq, bq, pq, NN, HID, HID);
            sgemm_nt_bias<<<ggh, 256>>>(in, Wk, bk, pk, NN, HID, HID);
            sgemm_nt_bias<<<ggh, 256>>>(in, Wv, bv, pv, NN, HID, HID);
            sgemm_nt_bias<<<ggh, 256>>>(in, Ws, bs, out, NN, HID, HID);  // skip -> aggregator init
            init_seg<<<nsblk, 256>>>(pamax, pdenom);
            edge_alpha<<<ewblk, 256>>>(pq, pk, src, dst, eat, We, palpha, pamax);
            edge_ex<<<esblk, 256>>>(dst, palpha, pamax, pdenom);
            edge_msg<<<ewblk, 256>>>(pv, src, dst, eat, We, palpha, pdenom, out);
            leaky_relu_k<<<nhblk, 256>>>(out);
        }
    }

    // ---------------- temporal attention + top-3 ----------------
    attn_topk<<<nwblk, 256>>>(ph, aW, ab, phattn);

    // ---------------- output TransformerConv (128 -> 1) ----------------
    {
        const int* src = ei + (size_t)(T_STEPS - 1) * 2 * EE;
        const int* dst = src + EE;
        const float* eat = ea + (size_t)(T_STEPS - 1) * EE;
        outconv_node<<<nwblk, 256>>>(phattn, oWq, obq, oWk, obk, oWv, obv, oWs, obs,
                                     pq, pk, pv, outp);
        init_seg<<<nsblk, 256>>>(pamax, pdenom);
        oc_alpha<<<esblk, 256>>>(pq, pk, src, dst, eat, oWe, palpha, pamax);
        edge_ex<<<esblk, 256>>>(dst, palpha, pamax, pdenom);
        oc_msg<<<esblk, 256>>>(pv, src, dst, eat, oWe, palpha, pdenom, outp);
    }
}